// round 3
// baseline (speedup 1.0000x reference)
#include <cuda_runtime.h>
#include <math_constants.h>

#define N 512
#define D 64
#define MAX_STEPS 10
#define NBLK 256

// ---- persistent scratch (no allocations allowed) ----
__device__ float        g_p[N];
__device__ float        g_arr[N];
__device__ unsigned int g_cand[N];
__device__ float        g_rowconst[N * D];  // nf[i]@W1[0:64] + b1
__device__ float        g_Bt[D * N];        // (nf[j]@W1[64:128]) transposed: [k][j]
__device__ float        g_f0[N];            // node_features[:,0]
__device__ int          g_bar_count;        // zero-init; self-resetting
__device__ volatile int g_bar_gen;          // monotonic generation

// ---------------------------------------------------------------------------
__global__ void k_init_state(const int* __restrict__ shock, int n_shock) {
    int t = threadIdx.x;
    if (t < N) { g_p[t] = 0.f; g_arr[t] = CUDART_INF_F; g_cand[t] = 0u; }
    __syncthreads();
    if (t < n_shock) { int s = shock[t]; g_p[s] = 1.f; g_arr[s] = 0.f; }
}

// 128 blocks x 256 = 32768 threads; each computes one elem of rowconst and Bt.
__global__ void k_init_ab(const float* __restrict__ nf,
                          const float* __restrict__ W1,
                          const float* __restrict__ b1) {
    int gid = blockIdx.x * 256 + threadIdx.x;     // < 32768
    int i = gid >> 6, k = gid & 63;
    float accA = b1[k];
#pragma unroll 8
    for (int d = 0; d < D; d++) accA = fmaf(nf[i * D + d], W1[d * D + k], accA);
    g_rowconst[gid] = accA;

    int j = gid & (N - 1), kk = gid >> 9;          // kk < 64
    float accB = 0.f;
#pragma unroll 8
    for (int d = 0; d < D; d++) accB = fmaf(nf[j * D + d], W1[(D + d) * D + kk], accB);
    g_Bt[kk * N + j] = accB;

    if (gid < N) g_f0[gid] = nf[gid * D];
}

// ---------------------------------------------------------------------------
__device__ __forceinline__ void grid_barrier() {
    __syncthreads();
    if (threadIdx.x == 0) {
        __threadfence();                       // publish + (gpu scope) L1 invalidate
        int gen = g_bar_gen;
        if (atomicAdd(&g_bar_count, 1) == NBLK - 1) {
            g_bar_count = 0;
            __threadfence();
            g_bar_gen = gen + 1;
        } else {
            while (g_bar_gen == gen) { __nanosleep(64); }
        }
        __threadfence();                       // acquire side: L1 invalidate
    }
    __syncthreads();
}

// ---------------------------------------------------------------------------
// Persistent kernel. Block b owns j-tile (b&15)*32 and i-tiles (b>>4)+16*{0..3}.
// All step-invariant data staged in smem once; 10 steps with 2 grid barriers each.
__global__ void __launch_bounds__(256, 2)
k_persist(const float* __restrict__ cgm, const float* __restrict__ W1,
          const float* __restrict__ W2,  const float* __restrict__ b2,
          const float* __restrict__ W3,  const float* __restrict__ b3,
          float* __restrict__ out) {
    __shared__ __align__(16) float s_w2[D * 32];   // W2[k][m]
    __shared__ float s_bt[D * 32];                 // Bt tile [k][lane]
    __shared__ float s_rc[4 * 8 * D];              // rowconst, 4 i-tiles
    __shared__ float s_rv[4 * 8 * D];              // per-step row vector
    __shared__ float s_cg[4 * 8 * 32];             // cg tiles
    __shared__ float2 s_wp[D];                     // (w128[k], w131[k])
    __shared__ float s_w129[D], s_w130[D];
    __shared__ float s_w3[32];
    __shared__ unsigned long long s_b2p[16];       // b2 packed pairs
    __shared__ float s_f0i[32], s_f0j[32], s_pi[32];
    __shared__ unsigned int s_cand[32];
    __shared__ float s_b3;

    int tid = threadIdx.x, b = blockIdx.x;
    int warp = tid >> 5, lane = tid & 31;
    int j0 = (b & 15) * 32;
    int ib = b >> 4;                               // 0..15

    // ---- one-time prologue ----
    for (int idx = tid; idx < D * 32; idx += 256) {
        s_w2[idx] = W2[idx];
        int kk = idx >> 5, jl = idx & 31;
        s_bt[idx] = g_Bt[kk * N + j0 + jl];
    }
    for (int idx = tid; idx < 2048; idx += 256) {
        int t = idx >> 9, rk = idx & 511;
        int gi = (ib + 16 * t) * 8 + (rk >> 6);
        s_rc[idx] = g_rowconst[gi * D + (rk & 63)];
    }
    for (int idx = tid; idx < 1024; idx += 256) {
        int t = idx >> 8, rl = idx & 255;
        int gi = (ib + 16 * t) * 8 + (rl >> 5);
        s_cg[idx] = cgm[gi * N + j0 + (rl & 31)];
    }
    if (tid < D) {
        s_wp[tid]  = make_float2(W1[128 * D + tid], W1[131 * D + tid]);
        s_w129[tid] = W1[129 * D + tid];
        s_w130[tid] = W1[130 * D + tid];
    }
    if (tid < 32) {
        s_w3[tid] = W3[tid];
        int gi = (ib + 16 * (tid >> 3)) * 8 + (tid & 7);
        s_f0i[tid] = g_f0[gi];
        s_f0j[tid] = g_f0[j0 + tid];
    }
    if (tid < 16) {
        unsigned long long pk;
        asm("mov.b64 %0, {%1, %2};" : "=l"(pk) : "f"(b2[2 * tid]), "f"(b2[2 * tid + 1]));
        s_b2p[tid] = pk;
    }
    if (tid == 0) s_b3 = b3[0];
    __syncthreads();

    // ---- step loop ----
    for (int s = 0; s < MAX_STEPS; s++) {
        float sf = (float)s * (1.0f / MAX_STEPS);
        if (tid < 32) {
            int gi = (ib + 16 * (tid >> 3)) * 8 + (tid & 7);
            s_pi[tid] = g_p[gi];
            s_cand[tid] = 0u;
        }
        __syncthreads();
        for (int idx = tid; idx < 2048; idx += 256) {
            int r = idx >> 6, k = idx & 63;
            s_rv[idx] = fmaf(s_pi[r], s_w129[k], fmaf(sf, s_w130[k], s_rc[idx]));
        }
        __syncthreads();

#pragma unroll
        for (int t = 0; t < 4; t++) {
            float p_i = s_pi[t * 8 + warp];
            if (p_i > 0.f) {
                float cg = s_cg[t * 256 + warp * 32 + lane];
                float fd = fabsf(s_f0i[t * 8 + warp] - s_f0j[lane]);
                unsigned long long h2[16];
#pragma unroll
                for (int q = 0; q < 16; q++) h2[q] = s_b2p[q];
                const float* rv = &s_rv[(t * 8 + warp) * D];
#pragma unroll 4
                for (int k = 0; k < D; k++) {
                    float2 wp = s_wp[k];
                    float h1 = rv[k] + s_bt[(k << 5) + lane];
                    h1 = fmaf(cg, wp.x, h1);
                    h1 = fmaf(fd, wp.y, h1);
                    h1 = fmaxf(h1, 0.f);
                    unsigned long long h1x2;
                    asm("mov.b64 %0, {%1, %1};" : "=l"(h1x2) : "f"(h1));
                    const ulonglong2* w2p = reinterpret_cast<const ulonglong2*>(&s_w2[k << 5]);
#pragma unroll
                    for (int q = 0; q < 8; q++) {
                        ulonglong2 v = w2p[q];   // LDS.128
                        asm("fma.rn.f32x2 %0, %1, %2, %0;"
                            : "+l"(h2[2 * q])     : "l"(h1x2), "l"(v.x));
                        asm("fma.rn.f32x2 %0, %1, %2, %0;"
                            : "+l"(h2[2 * q + 1]) : "l"(h1x2), "l"(v.y));
                    }
                }
                float z = s_b3;
#pragma unroll
                for (int q = 0; q < 16; q++) {
                    float lo, hi;
                    asm("mov.b64 {%0, %1}, %2;" : "=f"(lo), "=f"(hi) : "l"(h2[q]));
                    z = fmaf(fmaxf(lo, 0.f), s_w3[2 * q], z);
                    z = fmaf(fmaxf(hi, 0.f), s_w3[2 * q + 1], z);
                }
                float tr = 1.f / (1.f + __expf(-z));
                float val = (cg > 0.f) ? p_i * tr * cg : 0.f;
                if (val > 0.f) atomicMax(&s_cand[lane], __float_as_uint(val));
            }
        }
        __syncthreads();
        if (tid < 32) {
            unsigned v = s_cand[tid];
            if (v) atomicMax(&g_cand[j0 + tid], v);
            __threadfence();
        }
        grid_barrier();

        if (b == 0) {                       // scalar update phase
            for (int j = tid; j < N; j += 256) {
                float cand = __uint_as_float(g_cand[j]);
                g_cand[j] = 0u;
                float p = g_p[j], a = g_arr[j];
                if (cand > p) { p = cand; a = fminf(a, (float)(s + 1)); }
                g_p[j] = p; g_arr[j] = a;
                if (s == MAX_STEPS - 1) { out[j] = p; out[N + j] = a; }
            }
            __threadfence();
        }
        grid_barrier();
    }
}

// ---------------------------------------------------------------------------
extern "C" void kernel_launch(void* const* d_in, const int* in_sizes, int n_in,
                              void* d_out, int out_size) {
    const float* cg    = (const float*)d_in[0];
    const float* nf    = (const float*)d_in[1];
    const int*   shock = (const int*)  d_in[2];
    const float* W1    = (const float*)d_in[3];
    const float* b1    = (const float*)d_in[4];
    const float* W2    = (const float*)d_in[5];
    const float* b2    = (const float*)d_in[6];
    const float* W3    = (const float*)d_in[7];
    const float* b3    = (const float*)d_in[8];
    float* out = (float*)d_out;

    k_init_state<<<1, 512>>>(shock, in_sizes[2]);
    k_init_ab<<<128, 256>>>(nf, W1, b1);
    k_persist<<<NBLK, 256>>>(cg, W1, W2, b2, W3, b3, out);
}

// round 4
// speedup vs baseline: 1.1301x; 1.1301x over previous
#include <cuda_runtime.h>
#include <math_constants.h>

#define N 512
#define D 64
#define MAX_STEPS 10

// ---- persistent scratch (no allocations allowed) ----
__device__ float        g_p0[N];
__device__ unsigned int g_cand[MAX_STEPS][N];   // per-step candidate maxima (float bits)
__device__ float        g_rowconst[N * D];      // nf[i]@W1[0:64] + b1
__device__ float        g_Bt[D * N];            // (nf[j]@W1[64:128])^T : [k][j]
__device__ float        g_f0[N];                // node_features[:,0]

// ---------------------------------------------------------------------------
__global__ void k_init_state(const int* __restrict__ shock, int n_shock) {
    int t = threadIdx.x;                    // 512 threads
    if (t < N) g_p0[t] = 0.f;
    unsigned int* c = &g_cand[0][0];
    for (int idx = t; idx < MAX_STEPS * N; idx += 512) c[idx] = 0u;
    __syncthreads();
    if (t < n_shock) g_p0[shock[t]] = 1.f;
}

// 128 blocks x 256: one elem of rowconst and Bt each.
__global__ void k_init_ab(const float* __restrict__ nf,
                          const float* __restrict__ W1,
                          const float* __restrict__ b1) {
    int gid = blockIdx.x * 256 + threadIdx.x;      // < 32768
    int i = gid >> 6, k = gid & 63;
    float accA = b1[k];
#pragma unroll 8
    for (int d = 0; d < D; d++) accA = fmaf(nf[i * D + d], W1[d * D + k], accA);
    g_rowconst[gid] = accA;

    int j = gid & (N - 1), kk = gid >> 9;
    float accB = 0.f;
#pragma unroll 8
    for (int d = 0; d < D; d++) accB = fmaf(nf[j * D + d], W1[(D + d) * D + kk], accB);
    g_Bt[kk * N + j] = accB;

    if (gid < N) g_f0[gid] = nf[gid * D];
}

// ---------------------------------------------------------------------------
// Step kernel. Block = 8 src rows x 32 targets. Reconstructs p_s from the
// per-step cand buffers (no update kernel needed). Writes g_cand[step].
__global__ void __launch_bounds__(256, 3)
k_edges(const float* __restrict__ cgm, const float* __restrict__ W1,
        const float* __restrict__ W2,  const float* __restrict__ b2,
        const float* __restrict__ W3,  const float* __restrict__ b3,
        int step, float sf) {
    __shared__ __align__(16) float s_w2[D * 32];   // W2[k][m]
    __shared__ __align__(16) float s_bt2[D * 32];  // Bt interleaved: [k2][lane] float2
    __shared__ __align__(16) float s_rv[8 * D];    // per-(row,k) affine row vector
    __shared__ __align__(16) float s_wq[2 * D];    // (w128[k], w131[k]) interleaved
    __shared__ float s_w3[32];
    __shared__ unsigned long long s_b2p[16];       // b2 packed pairs
    __shared__ float s_f0i[8], s_f0j[32], s_pi[8];
    __shared__ unsigned int s_cand[32];
    __shared__ float s_b3;
    __shared__ int s_alive;

    int tid = threadIdx.x;
    int warp = tid >> 5, lane = tid & 31;
    int j0 = blockIdx.x * 32;
    int i0 = blockIdx.y * 8;

    if (tid == 0) s_alive = 0;
    __syncthreads();
    if (tid < 8) {
        float p = g_p0[i0 + tid];                  // replay: p_s = max(p0, cand_0..s-1)
        for (int s = 0; s < step; s++)
            p = fmaxf(p, __uint_as_float(g_cand[s][i0 + tid]));
        s_pi[tid] = p;
        s_f0i[tid] = g_f0[i0 + tid];
        if (p > 0.f) atomicExch(&s_alive, 1);
    }
    if (tid < 32) { s_f0j[tid] = g_f0[j0 + tid]; s_w3[tid] = W3[tid]; s_cand[tid] = 0u; }
    __syncthreads();
    if (!s_alive) return;                          // dead block: skip tile loads too

    {   // heavy tile loads
        const float4* W24 = (const float4*)W2;
        float4* s_w24 = (float4*)s_w2;
        for (int idx = tid; idx < 512; idx += 256) s_w24[idx] = W24[idx];
        for (int idx = tid; idx < 2048; idx += 256) {
            int k = idx >> 5, l = idx & 31;        // interleave k-pairs
            s_bt2[((k >> 1) << 6) + (l << 1) + (k & 1)] = g_Bt[k * N + j0 + l];
        }
        for (int idx = tid; idx < 512; idx += 256) {
            int r = idx >> 6, k = idx & 63;
            s_rv[idx] = fmaf(s_pi[r], W1[129 * D + k],
                        fmaf(sf, W1[130 * D + k], g_rowconst[(i0 + r) * D + k]));
        }
        if (tid < 128) s_wq[tid] = W1[(128 + 3 * (tid & 1)) * D + (tid >> 1)];
        if (tid < 16) {
            unsigned long long pk;
            asm("mov.b64 %0, {%1, %2};" : "=l"(pk) : "f"(b2[2 * tid]), "f"(b2[2 * tid + 1]));
            s_b2p[tid] = pk;
        }
        if (tid == 0) s_b3 = b3[0];
    }
    __syncthreads();

    float p_i = s_pi[warp];
    float val = 0.f;
    if (p_i > 0.f) {
        float cg = cgm[(i0 + warp) * N + j0 + lane];
        float fd = fabsf(s_f0i[warp] - s_f0j[lane]);
        unsigned long long h2[16];
#pragma unroll
        for (int q = 0; q < 16; q++) h2[q] = s_b2p[q];
        const float4* wq4 = (const float4*)s_wq;
        const float2* bt2 = (const float2*)s_bt2;
        const float2* rv2 = (const float2*)(&s_rv[warp * D]);
#pragma unroll 4
        for (int k2 = 0; k2 < 32; k2++) {
            float4 wq = wq4[k2];                   // LDS.128 broadcast
            float2 bt = bt2[(k2 << 5) + lane];     // LDS.64 per-lane
            float2 rv = rv2[k2];                   // LDS.64 broadcast
            float h1a = fmaxf(fmaf(cg, wq.x, fmaf(fd, wq.y, rv.x + bt.x)), 0.f);
            float h1b = fmaxf(fmaf(cg, wq.z, fmaf(fd, wq.w, rv.y + bt.y)), 0.f);
            unsigned long long h1a2, h1b2;
            asm("mov.b64 %0, {%1, %1};" : "=l"(h1a2) : "f"(h1a));
            asm("mov.b64 %0, {%1, %1};" : "=l"(h1b2) : "f"(h1b));
            const ulonglong2* wa = (const ulonglong2*)&s_w2[(2 * k2) << 5];
            const ulonglong2* wb = (const ulonglong2*)&s_w2[(2 * k2 + 1) << 5];
#pragma unroll
            for (int q = 0; q < 8; q++) {
                ulonglong2 va = wa[q];             // LDS.128
                asm("fma.rn.f32x2 %0, %1, %2, %0;" : "+l"(h2[2 * q])     : "l"(h1a2), "l"(va.x));
                asm("fma.rn.f32x2 %0, %1, %2, %0;" : "+l"(h2[2 * q + 1]) : "l"(h1a2), "l"(va.y));
            }
#pragma unroll
            for (int q = 0; q < 8; q++) {
                ulonglong2 vb = wb[q];             // LDS.128
                asm("fma.rn.f32x2 %0, %1, %2, %0;" : "+l"(h2[2 * q])     : "l"(h1b2), "l"(vb.x));
                asm("fma.rn.f32x2 %0, %1, %2, %0;" : "+l"(h2[2 * q + 1]) : "l"(h1b2), "l"(vb.y));
            }
        }
        float z = s_b3;
#pragma unroll
        for (int q = 0; q < 16; q++) {
            float lo, hi;
            asm("mov.b64 {%0, %1}, %2;" : "=f"(lo), "=f"(hi) : "l"(h2[q]));
            z = fmaf(fmaxf(lo, 0.f), s_w3[2 * q], z);
            z = fmaf(fmaxf(hi, 0.f), s_w3[2 * q + 1], z);
        }
        float t = 1.f / (1.f + __expf(-z));
        if (cg > 0.f) val = p_i * t * cg;
    }
    if (val > 0.f) atomicMax(&s_cand[lane], __float_as_uint(val));   // >=0: uint==float order
    __syncthreads();
    if (tid < 32) {
        unsigned v = s_cand[tid];
        if (v) atomicMax(&g_cand[step][j0 + tid], v);
    }
}

// replay the 10-step max/arr recurrence exactly; write output
__global__ void k_final(float* __restrict__ out) {
    int j = threadIdx.x;                           // 512 threads
    float p = g_p0[j];
    float arr = (p > 0.f) ? 0.f : CUDART_INF_F;
#pragma unroll
    for (int s = 0; s < MAX_STEPS; s++) {
        float c = __uint_as_float(g_cand[s][j]);
        if (c > p) { p = c; arr = fminf(arr, (float)(s + 1)); }
    }
    out[j] = p; out[N + j] = arr;
}

// ---------------------------------------------------------------------------
extern "C" void kernel_launch(void* const* d_in, const int* in_sizes, int n_in,
                              void* d_out, int out_size) {
    const float* cg    = (const float*)d_in[0];
    const float* nf    = (const float*)d_in[1];
    const int*   shock = (const int*)  d_in[2];
    const float* W1    = (const float*)d_in[3];
    const float* b1    = (const float*)d_in[4];
    const float* W2    = (const float*)d_in[5];
    const float* b2    = (const float*)d_in[6];
    const float* W3    = (const float*)d_in[7];
    const float* b3    = (const float*)d_in[8];
    float* out = (float*)d_out;

    k_init_state<<<1, 512>>>(shock, in_sizes[2]);
    k_init_ab<<<128, 256>>>(nf, W1, b1);
    for (int s = 0; s < MAX_STEPS; s++)
        k_edges<<<dim3(16, 64), 256>>>(cg, W1, W2, b2, W3, b3,
                                       s, (float)s / (float)MAX_STEPS);
    k_final<<<1, 512>>>(out);
}

// round 5
// speedup vs baseline: 1.3695x; 1.2118x over previous
#include <cuda_runtime.h>
#include <math_constants.h>

#define N 512
#define D 64
#define MAX_STEPS 10

// ---- persistent scratch (no allocations allowed) ----
__device__ float        g_p0[N];
__device__ unsigned int g_cand[MAX_STEPS][N];   // per-step candidate maxima (float bits)
__device__ float        g_rowconst[N * D];      // nf[i]@W1[0:64] + b1
__device__ float        g_Bt[D * N];            // (nf[j]@W1[64:128])^T : [k][j]
__device__ float        g_f0[N];                // node_features[:,0]

// ---------------------------------------------------------------------------
__global__ void k_init_state(const int* __restrict__ shock, int n_shock) {
    int t = threadIdx.x;                    // 512 threads
    if (t < N) g_p0[t] = 0.f;
    unsigned int* c = &g_cand[0][0];
    for (int idx = t; idx < MAX_STEPS * N; idx += 512) c[idx] = 0u;
    __syncthreads();
    if (t < n_shock) g_p0[shock[t]] = 1.f;
}

// 128 blocks x 256: one elem of rowconst and Bt each.
__global__ void k_init_ab(const float* __restrict__ nf,
                          const float* __restrict__ W1,
                          const float* __restrict__ b1) {
    int gid = blockIdx.x * 256 + threadIdx.x;      // < 32768
    int i = gid >> 6, k = gid & 63;
    float accA = b1[k];
#pragma unroll 8
    for (int d = 0; d < D; d++) accA = fmaf(nf[i * D + d], W1[d * D + k], accA);
    g_rowconst[gid] = accA;

    int j = gid & (N - 1), kk = gid >> 9;
    float accB = 0.f;
#pragma unroll 8
    for (int d = 0; d < D; d++) accB = fmaf(nf[j * D + d], W1[(D + d) * D + kk], accB);
    g_Bt[kk * N + j] = accB;

    if (gid < N) g_f0[gid] = nf[gid * D];
}

// ---------------------------------------------------------------------------
// Step kernel. Block = 16 src rows x 32 targets; each thread owns TWO edges
// (rows warp and warp+8, same j) so every s_w2 LDS.128 feeds 4 FFMA2.
__global__ void __launch_bounds__(256, 2)
k_edges(const float* __restrict__ cgm, const float* __restrict__ W1,
        const float* __restrict__ W2,  const float* __restrict__ b2,
        const float* __restrict__ W3,  const float* __restrict__ b3,
        int step, float sf) {
    __shared__ __align__(16) float s_w2[D * 32];   // W2[k][m]
    __shared__ __align__(16) float s_bt2[D * 32];  // Bt interleaved: [k2][lane] float2
    __shared__ __align__(16) float s_rv[16 * D];   // per-(row,k) affine row vector
    __shared__ __align__(16) float s_wq[2 * D];    // (w128[k], w131[k]) interleaved
    __shared__ float s_w3[32];
    __shared__ unsigned long long s_b2p[16];       // b2 packed pairs
    __shared__ float s_f0i[16], s_f0j[32], s_pi[16];
    __shared__ unsigned int s_cand[32];
    __shared__ float s_b3;
    __shared__ int s_alive;

    int tid = threadIdx.x;
    int warp = tid >> 5, lane = tid & 31;
    int j0 = blockIdx.x * 32;
    int i0 = blockIdx.y * 16;

    if (tid == 0) s_alive = 0;
    __syncthreads();
    if (tid < 16) {
        float p = g_p0[i0 + tid];                  // replay: p_s = max(p0, cand_0..s-1)
        for (int s = 0; s < step; s++)
            p = fmaxf(p, __uint_as_float(g_cand[s][i0 + tid]));
        s_pi[tid] = p;
        s_f0i[tid] = g_f0[i0 + tid];
        if (p > 0.f) atomicExch(&s_alive, 1);
    }
    if (tid < 32) { s_f0j[tid] = g_f0[j0 + tid]; s_w3[tid] = W3[tid]; s_cand[tid] = 0u; }
    __syncthreads();
    if (!s_alive) return;                          // dead block: skip tile loads too

    {   // heavy tile loads
        const float4* W24 = (const float4*)W2;
        float4* s_w24 = (float4*)s_w2;
        for (int idx = tid; idx < 512; idx += 256) s_w24[idx] = W24[idx];
        for (int idx = tid; idx < 2048; idx += 256) {
            int k = idx >> 5, l = idx & 31;        // interleave k-pairs
            s_bt2[((k >> 1) << 6) + (l << 1) + (k & 1)] = g_Bt[k * N + j0 + l];
        }
        for (int idx = tid; idx < 1024; idx += 256) {
            int r = idx >> 6, k = idx & 63;
            s_rv[idx] = fmaf(s_pi[r], W1[129 * D + k],
                        fmaf(sf, W1[130 * D + k], g_rowconst[(i0 + r) * D + k]));
        }
        if (tid < 128) s_wq[tid] = W1[(128 + 3 * (tid & 1)) * D + (tid >> 1)];
        if (tid < 16) {
            unsigned long long pk;
            asm("mov.b64 %0, {%1, %2};" : "=l"(pk) : "f"(b2[2 * tid]), "f"(b2[2 * tid + 1]));
            s_b2p[tid] = pk;
        }
        if (tid == 0) s_b3 = b3[0];
    }
    __syncthreads();

    int ra = warp, rb = warp + 8;
    float p_ia = s_pi[ra], p_ib = s_pi[rb];
    if (p_ia > 0.f || p_ib > 0.f) {
        float cga = cgm[(i0 + ra) * N + j0 + lane];
        float cgb = cgm[(i0 + rb) * N + j0 + lane];
        float fda = fabsf(s_f0i[ra] - s_f0j[lane]);
        float fdb = fabsf(s_f0i[rb] - s_f0j[lane]);
        unsigned long long h2a[16], h2b[16];
#pragma unroll
        for (int q = 0; q < 16; q++) { h2a[q] = s_b2p[q]; h2b[q] = s_b2p[q]; }
        const float4* wq4 = (const float4*)s_wq;
        const float2* bt2 = (const float2*)s_bt2;
        const float2* rva2 = (const float2*)(&s_rv[ra * D]);
        const float2* rvb2 = (const float2*)(&s_rv[rb * D]);
#pragma unroll 2
        for (int k2 = 0; k2 < 32; k2++) {
            float4 wq = wq4[k2];                   // LDS.128 broadcast
            float2 bt = bt2[(k2 << 5) + lane];     // LDS.64 per-lane (shared by both rows)
            float2 rva = rva2[k2];                 // LDS.64 broadcast
            float2 rvb = rvb2[k2];
            float h1a0 = fmaxf(fmaf(cga, wq.x, fmaf(fda, wq.y, rva.x + bt.x)), 0.f);
            float h1a1 = fmaxf(fmaf(cga, wq.z, fmaf(fda, wq.w, rva.y + bt.y)), 0.f);
            float h1b0 = fmaxf(fmaf(cgb, wq.x, fmaf(fdb, wq.y, rvb.x + bt.x)), 0.f);
            float h1b1 = fmaxf(fmaf(cgb, wq.z, fmaf(fdb, wq.w, rvb.y + bt.y)), 0.f);
            unsigned long long a0, a1, b0, b1;
            asm("mov.b64 %0, {%1, %1};" : "=l"(a0) : "f"(h1a0));
            asm("mov.b64 %0, {%1, %1};" : "=l"(a1) : "f"(h1a1));
            asm("mov.b64 %0, {%1, %1};" : "=l"(b0) : "f"(h1b0));
            asm("mov.b64 %0, {%1, %1};" : "=l"(b1) : "f"(h1b1));
            const ulonglong2* w0 = (const ulonglong2*)&s_w2[(2 * k2) << 5];
            const ulonglong2* w1 = (const ulonglong2*)&s_w2[(2 * k2 + 1) << 5];
#pragma unroll
            for (int q = 0; q < 8; q++) {
                ulonglong2 v = w0[q];              // LDS.128 -> 4 FFMA2
                asm("fma.rn.f32x2 %0, %1, %2, %0;" : "+l"(h2a[2 * q])     : "l"(a0), "l"(v.x));
                asm("fma.rn.f32x2 %0, %1, %2, %0;" : "+l"(h2a[2 * q + 1]) : "l"(a0), "l"(v.y));
                asm("fma.rn.f32x2 %0, %1, %2, %0;" : "+l"(h2b[2 * q])     : "l"(b0), "l"(v.x));
                asm("fma.rn.f32x2 %0, %1, %2, %0;" : "+l"(h2b[2 * q + 1]) : "l"(b0), "l"(v.y));
            }
#pragma unroll
            for (int q = 0; q < 8; q++) {
                ulonglong2 v = w1[q];              // LDS.128 -> 4 FFMA2
                asm("fma.rn.f32x2 %0, %1, %2, %0;" : "+l"(h2a[2 * q])     : "l"(a1), "l"(v.x));
                asm("fma.rn.f32x2 %0, %1, %2, %0;" : "+l"(h2a[2 * q + 1]) : "l"(a1), "l"(v.y));
                asm("fma.rn.f32x2 %0, %1, %2, %0;" : "+l"(h2b[2 * q])     : "l"(b1), "l"(v.x));
                asm("fma.rn.f32x2 %0, %1, %2, %0;" : "+l"(h2b[2 * q + 1]) : "l"(b1), "l"(v.y));
            }
        }
        float za = s_b3, zb = s_b3;
#pragma unroll
        for (int q = 0; q < 16; q++) {
            float lo, hi;
            asm("mov.b64 {%0, %1}, %2;" : "=f"(lo), "=f"(hi) : "l"(h2a[q]));
            za = fmaf(fmaxf(lo, 0.f), s_w3[2 * q], za);
            za = fmaf(fmaxf(hi, 0.f), s_w3[2 * q + 1], za);
            asm("mov.b64 {%0, %1}, %2;" : "=f"(lo), "=f"(hi) : "l"(h2b[q]));
            zb = fmaf(fmaxf(lo, 0.f), s_w3[2 * q], zb);
            zb = fmaf(fmaxf(hi, 0.f), s_w3[2 * q + 1], zb);
        }
        float ta = 1.f / (1.f + __expf(-za));
        float tb = 1.f / (1.f + __expf(-zb));
        float vala = (p_ia > 0.f && cga > 0.f) ? p_ia * ta * cga : 0.f;
        float valb = (p_ib > 0.f && cgb > 0.f) ? p_ib * tb * cgb : 0.f;
        float v = fmaxf(vala, valb);               // >=0: uint order == float order
        if (v > 0.f) atomicMax(&s_cand[lane], __float_as_uint(v));
    }
    __syncthreads();
    if (tid < 32) {
        unsigned v = s_cand[tid];
        if (v) atomicMax(&g_cand[step][j0 + tid], v);
    }
}

// replay the 10-step max/arr recurrence exactly; write output
__global__ void k_final(float* __restrict__ out) {
    int j = threadIdx.x;                           // 512 threads
    float p = g_p0[j];
    float arr = (p > 0.f) ? 0.f : CUDART_INF_F;
#pragma unroll
    for (int s = 0; s < MAX_STEPS; s++) {
        float c = __uint_as_float(g_cand[s][j]);
        if (c > p) { p = c; arr = fminf(arr, (float)(s + 1)); }
    }
    out[j] = p; out[N + j] = arr;
}

// ---------------------------------------------------------------------------
extern "C" void kernel_launch(void* const* d_in, const int* in_sizes, int n_in,
                              void* d_out, int out_size) {
    const float* cg    = (const float*)d_in[0];
    const float* nf    = (const float*)d_in[1];
    const int*   shock = (const int*)  d_in[2];
    const float* W1    = (const float*)d_in[3];
    const float* b1    = (const float*)d_in[4];
    const float* W2    = (const float*)d_in[5];
    const float* b2    = (const float*)d_in[6];
    const float* W3    = (const float*)d_in[7];
    const float* b3    = (const float*)d_in[8];
    float* out = (float*)d_out;

    k_init_state<<<1, 512>>>(shock, in_sizes[2]);
    k_init_ab<<<128, 256>>>(nf, W1, b1);
    for (int s = 0; s < MAX_STEPS; s++)
        k_edges<<<dim3(16, 32), 256>>>(cg, W1, W2, b2, W3, b3,
                                       s, (float)s / (float)MAX_STEPS);
    k_final<<<1, 512>>>(out);
}